// round 6
// baseline (speedup 1.0000x reference)
#include <cuda_runtime.h>
#include <cuda_bf16.h>
#include <math.h>
#include <stdint.h>

#define B_    2
#define L_    2048
#define DIM_  512
#define DIN_  1024
#define BL_   (B_*L_)
#define NGRID 8
#define INV_DEN 3.0303030303030303f

// ---------------- scratch (device globals; no allocation) ----------------
__device__ float g_u    [BL_*DIM_];
__device__ float g_xz   [(size_t)BL_*2048];
__device__ float g_xc   [BL_*DIN_];
__device__ float g_dbc  [BL_*64];
__device__ float g_dbcp [4*BL_*64];           // split-K partials
__device__ float g_delta[BL_*DIN_];
__device__ float g_y    [BL_*DIN_];
__device__ float g_x1   [BL_*DIM_];
__device__ float g_k    [BL_*DIM_];
__device__ float g_basis[(size_t)BL_*4096];

// ---------------- helpers ----------------
__device__ __forceinline__ float softplusf(float x){
    return fmaxf(x, 0.f) + log1pf(expf(-fabsf(x)));
}
__device__ __forceinline__ float siluf(float x){
    return x / (1.f + expf(-x));
}
__device__ __forceinline__ float tf32r(float x){
    uint32_t u;
    asm("cvt.rna.tf32.f32 %0, %1;" : "=r"(u) : "f"(x));
    return __uint_as_float(u);
}
__device__ __forceinline__ void mma_tf32(float (&d)[4], const uint32_t (&a)[4], const uint32_t (&b)[2]){
    asm volatile("mma.sync.aligned.m16n8k8.row.col.f32.tf32.tf32.f32 "
        "{%0,%1,%2,%3}, {%4,%5,%6,%7}, {%8,%9}, {%0,%1,%2,%3};\n"
        : "+f"(d[0]), "+f"(d[1]), "+f"(d[2]), "+f"(d[3])
        : "r"(a[0]), "r"(a[1]), "r"(a[2]), "r"(a[3]), "r"(b[0]), "r"(b[1]));
}

__device__ __forceinline__ void block_reduce2(float& s, float& ss, float* sh){
    #pragma unroll
    for (int o = 16; o; o >>= 1){
        s  += __shfl_xor_sync(0xffffffffu, s,  o);
        ss += __shfl_xor_sync(0xffffffffu, ss, o);
    }
    int w = threadIdx.x >> 5, l = threadIdx.x & 31;
    if (l == 0){ sh[w] = s; sh[8 + w] = ss; }
    __syncthreads();
    if (threadIdx.x < 32){
        float a = (l < 8) ? sh[l]     : 0.f;
        float b = (l < 8) ? sh[8 + l] : 0.f;
        #pragma unroll
        for (int o = 4; o; o >>= 1){
            a += __shfl_xor_sync(0xffffffffu, a, o);
            b += __shfl_xor_sync(0xffffffffu, b, o);
        }
        if (l == 0){ sh[16] = a; sh[17] = b; }
    }
    __syncthreads();
    s = sh[16]; ss = sh[17];
    __syncthreads();
}

// ---------------- double layernorm ----------------
__global__ void k_double_ln(const float* __restrict__ x,
                            const float* __restrict__ w1, const float* __restrict__ b1,
                            const float* __restrict__ w2, const float* __restrict__ b2,
                            float* __restrict__ out)
{
    __shared__ float sh[18];
    const int row = blockIdx.x;
    const int t = threadIdx.x;
    const float* xr = x + (size_t)row * DIM_;
    float v0 = xr[t], v1 = xr[t + 256];
    float s = v0 + v1, ss = v0*v0 + v1*v1;
    block_reduce2(s, ss, sh);
    float mu  = s * (1.f/DIM_);
    float var = ss * (1.f/DIM_) - mu*mu;
    float inv = rsqrtf(var + 1e-5f);
    float y0 = (v0 - mu) * inv * w1[t]       + b1[t];
    float y1 = (v1 - mu) * inv * w1[t + 256] + b1[t + 256];
    s = y0 + y1; ss = y0*y0 + y1*y1;
    block_reduce2(s, ss, sh);
    mu  = s * (1.f/DIM_);
    var = ss * (1.f/DIM_) - mu*mu;
    inv = rsqrtf(var + 1e-5f);
    out[(size_t)row*DIM_ + t]       = (y0 - mu) * inv * w2[t]       + b2[t];
    out[(size_t)row*DIM_ + t + 256] = (y1 - mu) * inv * w2[t + 256] + b2[t + 256];
}

// ---------------- tf32 tensor-core GEMM (round-4 inner loop, no prefetch) ----------------
// C[M,N] = A[M,K] * W[N,K]^T ; grid.z>1 => split-K partials at C + z*M*N.
// EPI: 0=+bias  1=+bias,softplus  2=+bias+residual
template<int BM, int BN, int EPI>
__global__ void __launch_bounds__(256)
k_gemm_tc(const float* __restrict__ A, int lda,
          const float* __restrict__ W,
          const float* __restrict__ bias,
          const float* __restrict__ res,
          float* __restrict__ C, int N, int K)
{
    constexpr int BK  = 16;
    constexpr int PAD = BK + 4;
    constexpr int WM  = BM / 2;
    constexpr int WN  = BN / 4;
    constexpr int MF  = WM / 16;
    constexpr int NF  = WN / 8;
    __shared__ float As[BM][PAD];
    __shared__ float Bs[BN][PAD];

    const int tid  = threadIdx.x;
    const int bm   = blockIdx.y * BM, bn = blockIdx.x * BN;
    const int wid  = tid >> 5, lane = tid & 31;
    const int wm   = wid >> 2, wn = wid & 3;
    const int g    = lane >> 2, tg = lane & 3;
    const int fr   = tid >> 2;
    const int fk   = (tid & 3) << 2;

    const int klen = K / gridDim.z;
    const int kb   = blockIdx.z * klen;
    const int kend = kb + klen;
    if (gridDim.z > 1) C += (size_t)blockIdx.z * (size_t)(gridDim.y * BM) * N;

    float acc[MF][NF][4];
    #pragma unroll
    for (int i = 0; i < MF; i++)
        #pragma unroll
        for (int j = 0; j < NF; j++)
            #pragma unroll
            for (int c = 0; c < 4; c++) acc[i][j][c] = 0.f;

    for (int k0 = kb; k0 < kend; k0 += BK){
        #pragma unroll
        for (int r0 = 0; r0 < BM; r0 += 64){
            float4 v = *(const float4*)&A[(size_t)(bm + r0 + fr) * lda + k0 + fk];
            *(float4*)&As[r0 + fr][fk] =
                make_float4(tf32r(v.x), tf32r(v.y), tf32r(v.z), tf32r(v.w));
        }
        #pragma unroll
        for (int r0 = 0; r0 < BN; r0 += 64){
            float4 v = *(const float4*)&W[(size_t)(bn + r0 + fr) * K + k0 + fk];
            *(float4*)&Bs[r0 + fr][fk] =
                make_float4(tf32r(v.x), tf32r(v.y), tf32r(v.z), tf32r(v.w));
        }
        __syncthreads();
        #pragma unroll
        for (int ks = 0; ks < BK; ks += 8){
            uint32_t a[MF][4], b[NF][2];
            #pragma unroll
            for (int mi = 0; mi < MF; mi++){
                int r = wm * WM + mi * 16 + g;
                a[mi][0] = __float_as_uint(As[r    ][ks + tg    ]);
                a[mi][1] = __float_as_uint(As[r + 8][ks + tg    ]);
                a[mi][2] = __float_as_uint(As[r    ][ks + tg + 4]);
                a[mi][3] = __float_as_uint(As[r + 8][ks + tg + 4]);
            }
            #pragma unroll
            for (int ni = 0; ni < NF; ni++){
                int c = wn * WN + ni * 8 + g;
                b[ni][0] = __float_as_uint(Bs[c][ks + tg    ]);
                b[ni][1] = __float_as_uint(Bs[c][ks + tg + 4]);
            }
            #pragma unroll
            for (int mi = 0; mi < MF; mi++)
                #pragma unroll
                for (int ni = 0; ni < NF; ni++)
                    mma_tf32(acc[mi][ni], a[mi], b[ni]);
        }
        __syncthreads();
    }

    #pragma unroll
    for (int mi = 0; mi < MF; mi++){
        int row0 = bm + wm * WM + mi * 16 + g;
        #pragma unroll
        for (int ni = 0; ni < NF; ni++){
            int col = bn + wn * WN + ni * 8 + 2 * tg;
            float b0 = bias ? bias[col] : 0.f, b1 = bias ? bias[col + 1] : 0.f;
            float v0 = acc[mi][ni][0] + b0, v1 = acc[mi][ni][1] + b1;
            float v2 = acc[mi][ni][2] + b0, v3 = acc[mi][ni][3] + b1;
            if (EPI == 1){ v0 = softplusf(v0); v1 = softplusf(v1); v2 = softplusf(v2); v3 = softplusf(v3); }
            if (EPI == 2){
                const float2 r0 = *(const float2*)&res[(size_t)row0 * N + col];
                const float2 r1 = *(const float2*)&res[(size_t)(row0 + 8) * N + col];
                v0 += r0.x; v1 += r0.y; v2 += r1.x; v3 += r1.y;
            }
            *(float2*)&C[(size_t)row0 * N + col]       = make_float2(v0, v1);
            *(float2*)&C[(size_t)(row0 + 8) * N + col] = make_float2(v2, v3);
        }
    }
}

// ---------------- reduce 4 split-K partials ----------------
__global__ void k_red4(const float* __restrict__ p, float* __restrict__ out)
{
    int idx = blockIdx.x * 256 + threadIdx.x;
    const float4* p4 = (const float4*)p;
    const int n4 = BL_ * 64 / 4;
    float4 a = p4[idx], b = p4[idx + n4], c = p4[idx + 2*n4], d = p4[idx + 3*n4];
    ((float4*)out)[idx] = make_float4(a.x+b.x+c.x+d.x, a.y+b.y+c.y+d.y,
                                      a.z+b.z+c.z+d.z, a.w+b.w+c.w+d.w);
}

// ---------------- causal depthwise conv (d_conv=4) + bias + SiLU ----------------
__global__ void k_conv_silu(const float* __restrict__ xz,
                            const float* __restrict__ cw,
                            const float* __restrict__ cb,
                            float* __restrict__ xc)
{
    int idx = blockIdx.x * 256 + threadIdx.x;
    int d = idx & (DIN_ - 1);
    int t = idx >> 10;
    int l = t & (L_ - 1);
    const float* w = cw + d * 4;
    float acc = cb[d];
    #pragma unroll
    for (int k = 0; k < 4; k++){
        int ls = l + k - 3;
        if (ls >= 0)
            acc = fmaf(xz[(size_t)(t + k - 3) * 2048 + d], w[k], acc);
    }
    xc[idx] = siluf(acc);
}

// ---------------- SSM scan fused with gate: y = (scan + D*xc) * silu(z) ----------------
__global__ void k_scan(const float* __restrict__ delta,
                       const float* __restrict__ dbc,
                       const float* __restrict__ xc,
                       const float* __restrict__ A_log,
                       const float* __restrict__ xz,
                       const float* __restrict__ Dp,
                       float* __restrict__ y)
{
    const int tid = threadIdx.x;
    const int n  = tid & 15;
    const int ch = blockIdx.x * 16 + (tid >> 4);
    const int b  = ch >> 10;
    const int d  = ch & (DIN_ - 1);
    const float A = -expf(A_log[d * 16 + n]);
    const float Dv = Dp[d];
    float h = 0.f;
    const int tbase = b * L_;
    for (int l = 0; l < L_; l++){
        const int t = tbase + l;
        float dlt = delta[(size_t)t * DIN_ + d];
        float xcv = xc   [(size_t)t * DIN_ + d];
        float Bv  = dbc[(size_t)t * 64 + 32 + n];
        float Cv  = dbc[(size_t)t * 64 + 48 + n];
        h = __expf(dlt * A) * h + dlt * Bv * xcv;
        float p = h * Cv;
        p += __shfl_xor_sync(0xffffffffu, p, 8);
        p += __shfl_xor_sync(0xffffffffu, p, 4);
        p += __shfl_xor_sync(0xffffffffu, p, 2);
        p += __shfl_xor_sync(0xffffffffu, p, 1);
        if (n == 0){
            float z = xz[(size_t)t * 2048 + DIN_ + d];
            y[(size_t)t * DIN_ + d] = (p + Dv * xcv) * siluf(z);
        }
    }
}

// ---------------- KAN basis ----------------
__global__ void k_basis(const float* __restrict__ k,
                        const float* __restrict__ grid,
                        float* __restrict__ basis)
{
    int idx = blockIdx.x * 256 + threadIdx.x;
    float kv = k[idx];
    float o[NGRID];
    #pragma unroll
    for (int g = 0; g < NGRID; g++){
        float tt = tanhf((kv - grid[g]) * INV_DEN);
        o[g] = 1.f - tt * tt;
    }
    float4* bp = (float4*)(basis + (size_t)idx * NGRID);
    bp[0] = make_float4(o[0], o[1], o[2], o[3]);
    bp[1] = make_float4(o[4], o[5], o[6], o[7]);
}

// ---------------- launch ----------------
extern "C" void kernel_launch(void* const* d_in, const int* in_sizes, int n_in,
                              void* d_out, int out_size)
{
    const float* x      = (const float*)d_in[0];
    const float* n1_w   = (const float*)d_in[1];
    const float* n1_b   = (const float*)d_in[2];
    const float* mn_w   = (const float*)d_in[3];
    const float* mn_b   = (const float*)d_in[4];
    const float* in_w   = (const float*)d_in[5];
    const float* in_b   = (const float*)d_in[6];
    const float* conv_w = (const float*)d_in[7];
    const float* conv_b = (const float*)d_in[8];
    const float* xp_w   = (const float*)d_in[9];
    const float* dt_w   = (const float*)d_in[10];
    const float* dt_b   = (const float*)d_in[11];
    const float* A_log  = (const float*)d_in[12];
    const float* D_par  = (const float*)d_in[13];
    const float* out_w  = (const float*)d_in[14];
    const float* out_b  = (const float*)d_in[15];
    const float* n2_w   = (const float*)d_in[16];
    const float* n2_b   = (const float*)d_in[17];
    const float* kn_w   = (const float*)d_in[18];
    const float* kn_b   = (const float*)d_in[19];
    const float* grid   = (const float*)d_in[20];
    const float* spl_w  = (const float*)d_in[21];

    float *u, *xz, *xc, *dbc, *dbcp, *delta, *y, *x1, *kb, *basis;
    cudaGetSymbolAddress((void**)&u,     g_u);
    cudaGetSymbolAddress((void**)&xz,    g_xz);
    cudaGetSymbolAddress((void**)&xc,    g_xc);
    cudaGetSymbolAddress((void**)&dbc,   g_dbc);
    cudaGetSymbolAddress((void**)&dbcp,  g_dbcp);
    cudaGetSymbolAddress((void**)&delta, g_delta);
    cudaGetSymbolAddress((void**)&y,     g_y);
    cudaGetSymbolAddress((void**)&x1,    g_x1);
    cudaGetSymbolAddress((void**)&kb,    g_k);
    cudaGetSymbolAddress((void**)&basis, g_basis);

    // 1. u = LN(LN(x))
    k_double_ln<<<BL_, 256>>>(x, n1_w, n1_b, mn_w, mn_b, u);
    // 2. xz = u @ in_w^T + in_b              (4096 x 2048 x 512)
    k_gemm_tc<128,128,0><<<dim3(16, 32), 256>>>(u, DIM_, in_w, in_b, nullptr, xz, 2048, DIM_);
    // 3. xc = silu(depthwise_conv(xm) + conv_b)
    k_conv_silu<<<BL_*DIN_/256, 256>>>(xz, conv_w, conv_b, xc);
    // 4. dbc = xc @ xp_w^T (split-K=4 partials, then reduce)   (4096 x 64 x 1024)
    k_gemm_tc<64,64,0><<<dim3(1, 64, 4), 256>>>(xc, DIN_, xp_w, nullptr, nullptr, dbcp, 64, DIN_);
    k_red4<<<BL_*64/4/256, 256>>>(dbcp, dbc);
    // 5. delta = softplus(dbc[:, :32] @ dt_w^T + dt_b)   (4096 x 1024 x 32)
    k_gemm_tc<128,128,1><<<dim3(8, 32), 256>>>(dbc, 64, dt_w, dt_b, nullptr, delta, DIN_, 32);
    // 6. scan + gate -> y
    k_scan<<<(B_*DIN_)/16, 256>>>(delta, dbc, xc, A_log, xz, D_par, y);
    // 7. x1 = x + y @ out_w^T + out_b        (4096 x 512 x 1024)
    k_gemm_tc<128,64,2><<<dim3(8, 32), 256>>>(y, DIN_, out_w, out_b, x, x1, DIM_, DIN_);
    // 8. k = LN(LN(x1))
    k_double_ln<<<BL_, 256>>>(x1, n2_w, n2_b, kn_w, kn_b, kb);
    // 9. basis
    k_basis<<<BL_*DIM_/256, 256>>>(kb, grid, basis);
    // 10. out = x1 + basis @ spl_w^T         (4096 x 512 x 4096)
    k_gemm_tc<128,64,2><<<dim3(8, 32), 256>>>(basis, DIM_*NGRID, spl_w, nullptr, x1,
                                              (float*)d_out, DIM_, DIM_*NGRID);
}

// round 7
// speedup vs baseline: 1.9613x; 1.9613x over previous
#include <cuda_runtime.h>
#include <cuda_bf16.h>
#include <math.h>
#include <stdint.h>

#define B_    2
#define L_    2048
#define DIM_  512
#define DIN_  1024
#define BL_   (B_*L_)
#define NGRID 8
#define INV_DEN 3.0303030303030303f

// ---------------- scratch (device globals; no allocation) ----------------
__device__ float g_u    [BL_*DIM_];
__device__ float g_xz   [(size_t)BL_*2048];
__device__ float g_xc   [BL_*DIN_];
__device__ float g_dbc  [BL_*64];
__device__ float g_dbcp [4*BL_*64];           // split-K partials
__device__ float g_delta[BL_*DIN_];
__device__ float g_y    [BL_*DIN_];
__device__ float g_x1   [BL_*DIM_];
__device__ float g_k    [BL_*DIM_];
__device__ float g_basis[(size_t)BL_*4096];

// ---------------- helpers ----------------
__device__ __forceinline__ float softplusf(float x){
    return fmaxf(x, 0.f) + log1pf(expf(-fabsf(x)));
}
__device__ __forceinline__ float siluf(float x){
    return x / (1.f + expf(-x));
}
__device__ __forceinline__ float tf32r(float x){
    uint32_t u;
    asm("cvt.rna.tf32.f32 %0, %1;" : "=r"(u) : "f"(x));
    return __uint_as_float(u);
}
__device__ __forceinline__ void mma_tf32(float (&d)[4], const uint32_t (&a)[4], const uint32_t (&b)[2]){
    asm volatile("mma.sync.aligned.m16n8k8.row.col.f32.tf32.tf32.f32 "
        "{%0,%1,%2,%3}, {%4,%5,%6,%7}, {%8,%9}, {%0,%1,%2,%3};\n"
        : "+f"(d[0]), "+f"(d[1]), "+f"(d[2]), "+f"(d[3])
        : "r"(a[0]), "r"(a[1]), "r"(a[2]), "r"(a[3]), "r"(b[0]), "r"(b[1]));
}

__device__ __forceinline__ void block_reduce2(float& s, float& ss, float* sh){
    #pragma unroll
    for (int o = 16; o; o >>= 1){
        s  += __shfl_xor_sync(0xffffffffu, s,  o);
        ss += __shfl_xor_sync(0xffffffffu, ss, o);
    }
    int w = threadIdx.x >> 5, l = threadIdx.x & 31;
    if (l == 0){ sh[w] = s; sh[8 + w] = ss; }
    __syncthreads();
    if (threadIdx.x < 32){
        float a = (l < 8) ? sh[l]     : 0.f;
        float b = (l < 8) ? sh[8 + l] : 0.f;
        #pragma unroll
        for (int o = 4; o; o >>= 1){
            a += __shfl_xor_sync(0xffffffffu, a, o);
            b += __shfl_xor_sync(0xffffffffu, b, o);
        }
        if (l == 0){ sh[16] = a; sh[17] = b; }
    }
    __syncthreads();
    s = sh[16]; ss = sh[17];
    __syncthreads();
}

// ---------------- double layernorm ----------------
__global__ void k_double_ln(const float* __restrict__ x,
                            const float* __restrict__ w1, const float* __restrict__ b1,
                            const float* __restrict__ w2, const float* __restrict__ b2,
                            float* __restrict__ out)
{
    __shared__ float sh[18];
    const int row = blockIdx.x;
    const int t = threadIdx.x;
    const float* xr = x + (size_t)row * DIM_;
    float v0 = xr[t], v1 = xr[t + 256];
    float s = v0 + v1, ss = v0*v0 + v1*v1;
    block_reduce2(s, ss, sh);
    float mu  = s * (1.f/DIM_);
    float var = ss * (1.f/DIM_) - mu*mu;
    float inv = rsqrtf(var + 1e-5f);
    float y0 = (v0 - mu) * inv * w1[t]       + b1[t];
    float y1 = (v1 - mu) * inv * w1[t + 256] + b1[t + 256];
    s = y0 + y1; ss = y0*y0 + y1*y1;
    block_reduce2(s, ss, sh);
    mu  = s * (1.f/DIM_);
    var = ss * (1.f/DIM_) - mu*mu;
    inv = rsqrtf(var + 1e-5f);
    out[(size_t)row*DIM_ + t]       = (y0 - mu) * inv * w2[t]       + b2[t];
    out[(size_t)row*DIM_ + t + 256] = (y1 - mu) * inv * w2[t + 256] + b2[t + 256];
}

// ---------------- tf32 tensor-core GEMM (round-4 inner loop) ----------------
// C[M,N] = A[M,K] * W[N,K]^T ; grid.z>1 => split-K partials at C + z*M*N.
// EPI: 0=+bias  1=+bias,softplus  2=+bias+residual
template<int BM, int BN, int EPI>
__global__ void __launch_bounds__(256)
k_gemm_tc(const float* __restrict__ A, int lda,
          const float* __restrict__ W,
          const float* __restrict__ bias,
          const float* __restrict__ res,
          float* __restrict__ C, int N, int K)
{
    constexpr int BK  = 16;
    constexpr int PAD = BK + 4;
    constexpr int WM  = BM / 2;
    constexpr int WN  = BN / 4;
    constexpr int MF  = WM / 16;
    constexpr int NF  = WN / 8;
    __shared__ float As[BM][PAD];
    __shared__ float Bs[BN][PAD];

    const int tid  = threadIdx.x;
    const int bm   = blockIdx.y * BM, bn = blockIdx.x * BN;
    const int wid  = tid >> 5, lane = tid & 31;
    const int wm   = wid >> 2, wn = wid & 3;
    const int g    = lane >> 2, tg = lane & 3;
    const int fr   = tid >> 2;
    const int fk   = (tid & 3) << 2;

    const int klen = K / gridDim.z;
    const int kb   = blockIdx.z * klen;
    const int kend = kb + klen;
    if (gridDim.z > 1) C += (size_t)blockIdx.z * (size_t)(gridDim.y * BM) * N;

    float acc[MF][NF][4];
    #pragma unroll
    for (int i = 0; i < MF; i++)
        #pragma unroll
        for (int j = 0; j < NF; j++)
            #pragma unroll
            for (int c = 0; c < 4; c++) acc[i][j][c] = 0.f;

    for (int k0 = kb; k0 < kend; k0 += BK){
        #pragma unroll
        for (int r0 = 0; r0 < BM; r0 += 64){
            float4 v = *(const float4*)&A[(size_t)(bm + r0 + fr) * lda + k0 + fk];
            *(float4*)&As[r0 + fr][fk] =
                make_float4(tf32r(v.x), tf32r(v.y), tf32r(v.z), tf32r(v.w));
        }
        #pragma unroll
        for (int r0 = 0; r0 < BN; r0 += 64){
            float4 v = *(const float4*)&W[(size_t)(bn + r0 + fr) * K + k0 + fk];
            *(float4*)&Bs[r0 + fr][fk] =
                make_float4(tf32r(v.x), tf32r(v.y), tf32r(v.z), tf32r(v.w));
        }
        __syncthreads();
        #pragma unroll
        for (int ks = 0; ks < BK; ks += 8){
            uint32_t a[MF][4], b[NF][2];
            #pragma unroll
            for (int mi = 0; mi < MF; mi++){
                int r = wm * WM + mi * 16 + g;
                a[mi][0] = __float_as_uint(As[r    ][ks + tg    ]);
                a[mi][1] = __float_as_uint(As[r + 8][ks + tg    ]);
                a[mi][2] = __float_as_uint(As[r    ][ks + tg + 4]);
                a[mi][3] = __float_as_uint(As[r + 8][ks + tg + 4]);
            }
            #pragma unroll
            for (int ni = 0; ni < NF; ni++){
                int c = wn * WN + ni * 8 + g;
                b[ni][0] = __float_as_uint(Bs[c][ks + tg    ]);
                b[ni][1] = __float_as_uint(Bs[c][ks + tg + 4]);
            }
            #pragma unroll
            for (int mi = 0; mi < MF; mi++)
                #pragma unroll
                for (int ni = 0; ni < NF; ni++)
                    mma_tf32(acc[mi][ni], a[mi], b[ni]);
        }
        __syncthreads();
    }

    #pragma unroll
    for (int mi = 0; mi < MF; mi++){
        int row0 = bm + wm * WM + mi * 16 + g;
        #pragma unroll
        for (int ni = 0; ni < NF; ni++){
            int col = bn + wn * WN + ni * 8 + 2 * tg;
            float b0 = bias ? bias[col] : 0.f, b1 = bias ? bias[col + 1] : 0.f;
            float v0 = acc[mi][ni][0] + b0, v1 = acc[mi][ni][1] + b1;
            float v2 = acc[mi][ni][2] + b0, v3 = acc[mi][ni][3] + b1;
            if (EPI == 1){ v0 = softplusf(v0); v1 = softplusf(v1); v2 = softplusf(v2); v3 = softplusf(v3); }
            if (EPI == 2){
                const float2 r0 = *(const float2*)&res[(size_t)row0 * N + col];
                const float2 r1 = *(const float2*)&res[(size_t)(row0 + 8) * N + col];
                v0 += r0.x; v1 += r0.y; v2 += r1.x; v3 += r1.y;
            }
            *(float2*)&C[(size_t)row0 * N + col]       = make_float2(v0, v1);
            *(float2*)&C[(size_t)(row0 + 8) * N + col] = make_float2(v2, v3);
        }
    }
}

// ---------------- reduce 4 split-K partials ----------------
__global__ void k_red4(const float* __restrict__ p, float* __restrict__ out)
{
    int idx = blockIdx.x * 256 + threadIdx.x;
    const float4* p4 = (const float4*)p;
    const int n4 = BL_ * 64 / 4;
    float4 a = p4[idx], b = p4[idx + n4], c = p4[idx + 2*n4], d = p4[idx + 3*n4];
    ((float4*)out)[idx] = make_float4(a.x+b.x+c.x+d.x, a.y+b.y+c.y+d.y,
                                      a.z+b.z+c.z+d.z, a.w+b.w+c.w+d.w);
}

// ---------------- causal depthwise conv (d_conv=4) + bias + SiLU ----------------
__global__ void k_conv_silu(const float* __restrict__ xz,
                            const float* __restrict__ cw,
                            const float* __restrict__ cb,
                            float* __restrict__ xc)
{
    int idx = blockIdx.x * 256 + threadIdx.x;
    int d = idx & (DIN_ - 1);
    int t = idx >> 10;
    int l = t & (L_ - 1);
    const float* w = cw + d * 4;
    float acc = cb[d];
    #pragma unroll
    for (int k = 0; k < 4; k++){
        int ls = l + k - 3;
        if (ls >= 0)
            acc = fmaf(xz[(size_t)(t + k - 3) * 2048 + d], w[k], acc);
    }
    xc[idx] = siluf(acc);
}

// ---------------- SSM sequential scan (store-only divergent branch) ----------------
__global__ void k_scan(const float* __restrict__ delta,
                       const float* __restrict__ dbc,
                       const float* __restrict__ xc,
                       const float* __restrict__ A_log,
                       float* __restrict__ y)
{
    const int tid = threadIdx.x;
    const int n  = tid & 15;
    const int ch = blockIdx.x * 16 + (tid >> 4);
    const int b  = ch >> 10;
    const int d  = ch & (DIN_ - 1);
    const float A = -expf(A_log[d * 16 + n]);
    float h = 0.f;
    const int tbase = b * L_;
    for (int l = 0; l < L_; l++){
        const int t = tbase + l;
        float dlt = delta[(size_t)t * DIN_ + d];
        float xcv = xc   [(size_t)t * DIN_ + d];
        float Bv  = dbc[(size_t)t * 64 + 32 + n];
        float Cv  = dbc[(size_t)t * 64 + 48 + n];
        h = __expf(dlt * A) * h + dlt * Bv * xcv;
        float p = h * Cv;
        p += __shfl_xor_sync(0xffffffffu, p, 8);
        p += __shfl_xor_sync(0xffffffffu, p, 4);
        p += __shfl_xor_sync(0xffffffffu, p, 2);
        p += __shfl_xor_sync(0xffffffffu, p, 1);
        if (n == 0) y[(size_t)t * DIN_ + d] = p;
    }
}

// ---------------- gate: y <- (y + D*xc) * silu(z) ----------------
__global__ void k_gate(float* __restrict__ y,
                       const float* __restrict__ xc,
                       const float* __restrict__ xz,
                       const float* __restrict__ Dp)
{
    int idx = blockIdx.x * 256 + threadIdx.x;
    int d = idx & (DIN_ - 1);
    int t = idx >> 10;
    float z  = xz[(size_t)t * 2048 + DIN_ + d];
    float yv = y[idx] + Dp[d] * xc[idx];
    y[idx] = yv * siluf(z);
}

// ---------------- KAN basis ----------------
__global__ void k_basis(const float* __restrict__ k,
                        const float* __restrict__ grid,
                        float* __restrict__ basis)
{
    int idx = blockIdx.x * 256 + threadIdx.x;
    float kv = k[idx];
    float o[NGRID];
    #pragma unroll
    for (int g = 0; g < NGRID; g++){
        float tt = tanhf((kv - grid[g]) * INV_DEN);
        o[g] = 1.f - tt * tt;
    }
    float4* bp = (float4*)(basis + (size_t)idx * NGRID);
    bp[0] = make_float4(o[0], o[1], o[2], o[3]);
    bp[1] = make_float4(o[4], o[5], o[6], o[7]);
}

// ---------------- launch ----------------
extern "C" void kernel_launch(void* const* d_in, const int* in_sizes, int n_in,
                              void* d_out, int out_size)
{
    const float* x      = (const float*)d_in[0];
    const float* n1_w   = (const float*)d_in[1];
    const float* n1_b   = (const float*)d_in[2];
    const float* mn_w   = (const float*)d_in[3];
    const float* mn_b   = (const float*)d_in[4];
    const float* in_w   = (const float*)d_in[5];
    const float* in_b   = (const float*)d_in[6];
    const float* conv_w = (const float*)d_in[7];
    const float* conv_b = (const float*)d_in[8];
    const float* xp_w   = (const float*)d_in[9];
    const float* dt_w   = (const float*)d_in[10];
    const float* dt_b   = (const float*)d_in[11];
    const float* A_log  = (const float*)d_in[12];
    const float* D_par  = (const float*)d_in[13];
    const float* out_w  = (const float*)d_in[14];
    const float* out_b  = (const float*)d_in[15];
    const float* n2_w   = (const float*)d_in[16];
    const float* n2_b   = (const float*)d_in[17];
    const float* kn_w   = (const float*)d_in[18];
    const float* kn_b   = (const float*)d_in[19];
    const float* grid   = (const float*)d_in[20];
    const float* spl_w  = (const float*)d_in[21];

    float *u, *xz, *xc, *dbc, *dbcp, *delta, *y, *x1, *kb, *basis;
    cudaGetSymbolAddress((void**)&u,     g_u);
    cudaGetSymbolAddress((void**)&xz,    g_xz);
    cudaGetSymbolAddress((void**)&xc,    g_xc);
    cudaGetSymbolAddress((void**)&dbc,   g_dbc);
    cudaGetSymbolAddress((void**)&dbcp,  g_dbcp);
    cudaGetSymbolAddress((void**)&delta, g_delta);
    cudaGetSymbolAddress((void**)&y,     g_y);
    cudaGetSymbolAddress((void**)&x1,    g_x1);
    cudaGetSymbolAddress((void**)&kb,    g_k);
    cudaGetSymbolAddress((void**)&basis, g_basis);

    // 1. u = LN(LN(x))
    k_double_ln<<<BL_, 256>>>(x, n1_w, n1_b, mn_w, mn_b, u);
    // 2. xz = u @ in_w^T + in_b              (4096 x 2048 x 512)
    k_gemm_tc<128,128,0><<<dim3(16, 32), 256>>>(u, DIM_, in_w, in_b, nullptr, xz, 2048, DIM_);
    // 3. xc = silu(depthwise_conv(xm) + conv_b)
    k_conv_silu<<<BL_*DIN_/256, 256>>>(xz, conv_w, conv_b, xc);
    // 4. dbc = xc @ xp_w^T (split-K=4 partials, then reduce)   (4096 x 64 x 1024)
    k_gemm_tc<64,64,0><<<dim3(1, 64, 4), 256>>>(xc, DIN_, xp_w, nullptr, nullptr, dbcp, 64, DIN_);
    k_red4<<<BL_*64/4/256, 256>>>(dbcp, dbc);
    // 5. delta = softplus(dbc[:, :32] @ dt_w^T + dt_b)   (4096 x 1024 x 32)
    k_gemm_tc<128,128,1><<<dim3(8, 32), 256>>>(dbc, 64, dt_w, dt_b, nullptr, delta, DIN_, 32);
    // 6. SSM scan -> y
    k_scan<<<(B_*DIN_)/16, 256>>>(delta, dbc, xc, A_log, y);
    // 7. gate
    k_gate<<<BL_*DIN_/256, 256>>>(y, xc, xz, D_par);
    // 8. x1 = x + y @ out_w^T + out_b        (4096 x 512 x 1024)
    k_gemm_tc<128,64,2><<<dim3(8, 32), 256>>>(y, DIN_, out_w, out_b, x, x1, DIM_, DIN_);
    // 9. k = LN(LN(x1))
    k_double_ln<<<BL_, 256>>>(x1, n2_w, n2_b, kn_w, kn_b, kb);
    // 10. basis
    k_basis<<<BL_*DIM_/256, 256>>>(kb, grid, basis);
    // 11. out = x1 + basis @ spl_w^T         (4096 x 512 x 4096)
    k_gemm_tc<128,64,2><<<dim3(8, 32), 256>>>(basis, DIM_*NGRID, spl_w, nullptr, x1,
                                              (float*)d_out, DIM_, DIM_*NGRID);
}

// round 8
// speedup vs baseline: 1.9944x; 1.0169x over previous
#include <cuda_runtime.h>
#include <cuda_bf16.h>
#include <math.h>
#include <stdint.h>

#define B_    2
#define L_    2048
#define DIM_  512
#define DIN_  1024
#define BL_   (B_*L_)
#define NGRID 8
#define INV_DEN 3.0303030303030303f

// ---------------- scratch (device globals; no allocation) ----------------
__device__ float g_u    [BL_*DIM_];
__device__ float g_xz   [(size_t)BL_*2048];
__device__ float g_xc   [BL_*DIN_];
__device__ float g_dbc  [BL_*64];
__device__ float g_dbcp [4*BL_*64];           // split-K partials
__device__ float g_delta[BL_*DIN_];
__device__ float g_y    [BL_*DIN_];
__device__ float g_x1   [BL_*DIM_];
__device__ float g_k    [BL_*DIM_];
__device__ float g_basis[(size_t)BL_*4096];

// ---------------- helpers ----------------
__device__ __forceinline__ float softplusf(float x){
    return fmaxf(x, 0.f) + log1pf(expf(-fabsf(x)));
}
__device__ __forceinline__ float siluf(float x){
    return x / (1.f + expf(-x));
}
__device__ __forceinline__ float tf32r(float x){
    uint32_t u;
    asm("cvt.rna.tf32.f32 %0, %1;" : "=r"(u) : "f"(x));
    return __uint_as_float(u);
}
__device__ __forceinline__ void mma_tf32(float (&d)[4], const uint32_t (&a)[4], const uint32_t (&b)[2]){
    asm volatile("mma.sync.aligned.m16n8k8.row.col.f32.tf32.tf32.f32 "
        "{%0,%1,%2,%3}, {%4,%5,%6,%7}, {%8,%9}, {%0,%1,%2,%3};\n"
        : "+f"(d[0]), "+f"(d[1]), "+f"(d[2]), "+f"(d[3])
        : "r"(a[0]), "r"(a[1]), "r"(a[2]), "r"(a[3]), "r"(b[0]), "r"(b[1]));
}

__device__ __forceinline__ void block_reduce2(float& s, float& ss, float* sh){
    #pragma unroll
    for (int o = 16; o; o >>= 1){
        s  += __shfl_xor_sync(0xffffffffu, s,  o);
        ss += __shfl_xor_sync(0xffffffffu, ss, o);
    }
    int w = threadIdx.x >> 5, l = threadIdx.x & 31;
    if (l == 0){ sh[w] = s; sh[8 + w] = ss; }
    __syncthreads();
    if (threadIdx.x < 32){
        float a = (l < 8) ? sh[l]     : 0.f;
        float b = (l < 8) ? sh[8 + l] : 0.f;
        #pragma unroll
        for (int o = 4; o; o >>= 1){
            a += __shfl_xor_sync(0xffffffffu, a, o);
            b += __shfl_xor_sync(0xffffffffu, b, o);
        }
        if (l == 0){ sh[16] = a; sh[17] = b; }
    }
    __syncthreads();
    s = sh[16]; ss = sh[17];
    __syncthreads();
}

// ---------------- double layernorm ----------------
__global__ void k_double_ln(const float* __restrict__ x,
                            const float* __restrict__ w1, const float* __restrict__ b1,
                            const float* __restrict__ w2, const float* __restrict__ b2,
                            float* __restrict__ out)
{
    __shared__ float sh[18];
    const int row = blockIdx.x;
    const int t = threadIdx.x;
    const float* xr = x + (size_t)row * DIM_;
    float v0 = xr[t], v1 = xr[t + 256];
    float s = v0 + v1, ss = v0*v0 + v1*v1;
    block_reduce2(s, ss, sh);
    float mu  = s * (1.f/DIM_);
    float var = ss * (1.f/DIM_) - mu*mu;
    float inv = rsqrtf(var + 1e-5f);
    float y0 = (v0 - mu) * inv * w1[t]       + b1[t];
    float y1 = (v1 - mu) * inv * w1[t + 256] + b1[t + 256];
    s = y0 + y1; ss = y0*y0 + y1*y1;
    block_reduce2(s, ss, sh);
    mu  = s * (1.f/DIM_);
    var = ss * (1.f/DIM_) - mu*mu;
    inv = rsqrtf(var + 1e-5f);
    out[(size_t)row*DIM_ + t]       = (y0 - mu) * inv * w2[t]       + b2[t];
    out[(size_t)row*DIM_ + t + 256] = (y1 - mu) * inv * w2[t + 256] + b2[t + 256];
}

// ---------------- tf32 tensor-core GEMM with register prefetch pipeline ----------------
// C[M,N] = A[M,K] * W[N,K]^T ; grid.z>1 => split-K partials at C + z*M*N.
// EPI: 0=+bias  1=+bias,softplus  2=+bias+residual
template<int BM, int BN, int EPI>
__global__ void __launch_bounds__(256)
k_gemm_tc(const float* __restrict__ A, int lda,
          const float* __restrict__ W,
          const float* __restrict__ bias,
          const float* __restrict__ res,
          float* __restrict__ C, int N, int K)
{
    constexpr int BK  = 16;
    constexpr int PAD = BK + 4;
    constexpr int WM  = BM / 2;
    constexpr int WN  = BN / 4;
    constexpr int MF  = WM / 16;
    constexpr int NF  = WN / 8;
    constexpr int RA  = BM / 64;
    constexpr int RB  = BN / 64;
    __shared__ float As[BM][PAD];
    __shared__ float Bs[BN][PAD];

    const int tid  = threadIdx.x;
    const int bm   = blockIdx.y * BM, bn = blockIdx.x * BN;
    const int wid  = tid >> 5, lane = tid & 31;
    const int wm   = wid >> 2, wn = wid & 3;
    const int g    = lane >> 2, tg = lane & 3;
    const int fr   = tid >> 2;
    const int fk   = (tid & 3) << 2;

    const int klen = K / gridDim.z;
    const int kb   = blockIdx.z * klen;
    const int kend = kb + klen;
    if (gridDim.z > 1) C += (size_t)blockIdx.z * (size_t)(gridDim.y * BM) * N;

    float acc[MF][NF][4];
    #pragma unroll
    for (int i = 0; i < MF; i++)
        #pragma unroll
        for (int j = 0; j < NF; j++)
            #pragma unroll
            for (int c = 0; c < 4; c++) acc[i][j][c] = 0.f;

    float4 rA[RA], rB[RB];
    #pragma unroll
    for (int i = 0; i < RA; i++)
        rA[i] = *(const float4*)&A[(size_t)(bm + i*64 + fr) * lda + kb + fk];
    #pragma unroll
    for (int i = 0; i < RB; i++)
        rB[i] = *(const float4*)&W[(size_t)(bn + i*64 + fr) * K + kb + fk];

    for (int k0 = kb; k0 < kend; k0 += BK){
        #pragma unroll
        for (int i = 0; i < RA; i++)
            *(float4*)&As[i*64 + fr][fk] =
                make_float4(tf32r(rA[i].x), tf32r(rA[i].y), tf32r(rA[i].z), tf32r(rA[i].w));
        #pragma unroll
        for (int i = 0; i < RB; i++)
            *(float4*)&Bs[i*64 + fr][fk] =
                make_float4(tf32r(rB[i].x), tf32r(rB[i].y), tf32r(rB[i].z), tf32r(rB[i].w));
        __syncthreads();
        if (k0 + BK < kend){
            #pragma unroll
            for (int i = 0; i < RA; i++)
                rA[i] = *(const float4*)&A[(size_t)(bm + i*64 + fr) * lda + k0 + BK + fk];
            #pragma unroll
            for (int i = 0; i < RB; i++)
                rB[i] = *(const float4*)&W[(size_t)(bn + i*64 + fr) * K + k0 + BK + fk];
        }
        #pragma unroll
        for (int ks = 0; ks < BK; ks += 8){
            uint32_t a[MF][4], b[NF][2];
            #pragma unroll
            for (int mi = 0; mi < MF; mi++){
                int r = wm * WM + mi * 16 + g;
                a[mi][0] = __float_as_uint(As[r    ][ks + tg    ]);
                a[mi][1] = __float_as_uint(As[r + 8][ks + tg    ]);
                a[mi][2] = __float_as_uint(As[r    ][ks + tg + 4]);
                a[mi][3] = __float_as_uint(As[r + 8][ks + tg + 4]);
            }
            #pragma unroll
            for (int ni = 0; ni < NF; ni++){
                int c = wn * WN + ni * 8 + g;
                b[ni][0] = __float_as_uint(Bs[c][ks + tg    ]);
                b[ni][1] = __float_as_uint(Bs[c][ks + tg + 4]);
            }
            #pragma unroll
            for (int mi = 0; mi < MF; mi++)
                #pragma unroll
                for (int ni = 0; ni < NF; ni++)
                    mma_tf32(acc[mi][ni], a[mi], b[ni]);
        }
        __syncthreads();
    }

    #pragma unroll
    for (int mi = 0; mi < MF; mi++){
        int row0 = bm + wm * WM + mi * 16 + g;
        #pragma unroll
        for (int ni = 0; ni < NF; ni++){
            int col = bn + wn * WN + ni * 8 + 2 * tg;
            float b0 = bias ? bias[col] : 0.f, b1 = bias ? bias[col + 1] : 0.f;
            float v0 = acc[mi][ni][0] + b0, v1 = acc[mi][ni][1] + b1;
            float v2 = acc[mi][ni][2] + b0, v3 = acc[mi][ni][3] + b1;
            if (EPI == 1){ v0 = softplusf(v0); v1 = softplusf(v1); v2 = softplusf(v2); v3 = softplusf(v3); }
            if (EPI == 2){
                const float2 r0 = *(const float2*)&res[(size_t)row0 * N + col];
                const float2 r1 = *(const float2*)&res[(size_t)(row0 + 8) * N + col];
                v0 += r0.x; v1 += r0.y; v2 += r1.x; v3 += r1.y;
            }
            *(float2*)&C[(size_t)row0 * N + col]       = make_float2(v0, v1);
            *(float2*)&C[(size_t)(row0 + 8) * N + col] = make_float2(v2, v3);
        }
    }
}

// ---------------- reduce 4 split-K partials ----------------
__global__ void k_red4(const float* __restrict__ p, float* __restrict__ out)
{
    int idx = blockIdx.x * 256 + threadIdx.x;
    const float4* p4 = (const float4*)p;
    const int n4 = BL_ * 64 / 4;
    float4 a = p4[idx], b = p4[idx + n4], c = p4[idx + 2*n4], d = p4[idx + 3*n4];
    ((float4*)out)[idx] = make_float4(a.x+b.x+c.x+d.x, a.y+b.y+c.y+d.y,
                                      a.z+b.z+c.z+d.z, a.w+b.w+c.w+d.w);
}

// ---------------- causal depthwise conv (d_conv=4) + bias + SiLU ----------------
__global__ void k_conv_silu(const float* __restrict__ xz,
                            const float* __restrict__ cw,
                            const float* __restrict__ cb,
                            float* __restrict__ xc)
{
    int idx = blockIdx.x * 256 + threadIdx.x;
    int d = idx & (DIN_ - 1);
    int t = idx >> 10;
    int l = t & (L_ - 1);
    const float* w = cw + d * 4;
    float acc = cb[d];
    #pragma unroll
    for (int k = 0; k < 4; k++){
        int ls = l + k - 3;
        if (ls >= 0)
            acc = fmaf(xz[(size_t)(t + k - 3) * 2048 + d], w[k], acc);
    }
    xc[idx] = siluf(acc);
}

// ---------------- SSM sequential scan (store-only divergent branch) ----------------
__global__ void k_scan(const float* __restrict__ delta,
                       const float* __restrict__ dbc,
                       const float* __restrict__ xc,
                       const float* __restrict__ A_log,
                       float* __restrict__ y)
{
    const int tid = threadIdx.x;
    const int n  = tid & 15;
    const int ch = blockIdx.x * 16 + (tid >> 4);
    const int b  = ch >> 10;
    const int d  = ch & (DIN_ - 1);
    const float A = -expf(A_log[d * 16 + n]);
    float h = 0.f;
    const int tbase = b * L_;
    for (int l = 0; l < L_; l++){
        const int t = tbase + l;
        float dlt = delta[(size_t)t * DIN_ + d];
        float xcv = xc   [(size_t)t * DIN_ + d];
        float Bv  = dbc[(size_t)t * 64 + 32 + n];
        float Cv  = dbc[(size_t)t * 64 + 48 + n];
        h = __expf(dlt * A) * h + dlt * Bv * xcv;
        float p = h * Cv;
        p += __shfl_xor_sync(0xffffffffu, p, 8);
        p += __shfl_xor_sync(0xffffffffu, p, 4);
        p += __shfl_xor_sync(0xffffffffu, p, 2);
        p += __shfl_xor_sync(0xffffffffu, p, 1);
        if (n == 0) y[(size_t)t * DIN_ + d] = p;
    }
}

// ---------------- gate: y <- (y + D*xc) * silu(z) ----------------
__global__ void k_gate(float* __restrict__ y,
                       const float* __restrict__ xc,
                       const float* __restrict__ xz,
                       const float* __restrict__ Dp)
{
    int idx = blockIdx.x * 256 + threadIdx.x;
    int d = idx & (DIN_ - 1);
    int t = idx >> 10;
    float z  = xz[(size_t)t * 2048 + DIN_ + d];
    float yv = y[idx] + Dp[d] * xc[idx];
    y[idx] = yv * siluf(z);
}

// ---------------- KAN basis ----------------
__global__ void k_basis(const float* __restrict__ k,
                        const float* __restrict__ grid,
                        float* __restrict__ basis)
{
    int idx = blockIdx.x * 256 + threadIdx.x;
    float kv = k[idx];
    float o[NGRID];
    #pragma unroll
    for (int g = 0; g < NGRID; g++){
        float tt = tanhf((kv - grid[g]) * INV_DEN);
        o[g] = 1.f - tt * tt;
    }
    float4* bp = (float4*)(basis + (size_t)idx * NGRID);
    bp[0] = make_float4(o[0], o[1], o[2], o[3]);
    bp[1] = make_float4(o[4], o[5], o[6], o[7]);
}

// ---------------- launch ----------------
extern "C" void kernel_launch(void* const* d_in, const int* in_sizes, int n_in,
                              void* d_out, int out_size)
{
    const float* x      = (const float*)d_in[0];
    const float* n1_w   = (const float*)d_in[1];
    const float* n1_b   = (const float*)d_in[2];
    const float* mn_w   = (const float*)d_in[3];
    const float* mn_b   = (const float*)d_in[4];
    const float* in_w   = (const float*)d_in[5];
    const float* in_b   = (const float*)d_in[6];
    const float* conv_w = (const float*)d_in[7];
    const float* conv_b = (const float*)d_in[8];
    const float* xp_w   = (const float*)d_in[9];
    const float* dt_w   = (const float*)d_in[10];
    const float* dt_b   = (const float*)d_in[11];
    const float* A_log  = (const float*)d_in[12];
    const float* D_par  = (const float*)d_in[13];
    const float* out_w  = (const float*)d_in[14];
    const float* out_b  = (const float*)d_in[15];
    const float* n2_w   = (const float*)d_in[16];
    const float* n2_b   = (const float*)d_in[17];
    const float* kn_w   = (const float*)d_in[18];
    const float* kn_b   = (const float*)d_in[19];
    const float* grid   = (const float*)d_in[20];
    const float* spl_w  = (const float*)d_in[21];

    float *u, *xz, *xc, *dbc, *dbcp, *delta, *y, *x1, *kb, *basis;
    cudaGetSymbolAddress((void**)&u,     g_u);
    cudaGetSymbolAddress((void**)&xz,    g_xz);
    cudaGetSymbolAddress((void**)&xc,    g_xc);
    cudaGetSymbolAddress((void**)&dbc,   g_dbc);
    cudaGetSymbolAddress((void**)&dbcp,  g_dbcp);
    cudaGetSymbolAddress((void**)&delta, g_delta);
    cudaGetSymbolAddress((void**)&y,     g_y);
    cudaGetSymbolAddress((void**)&x1,    g_x1);
    cudaGetSymbolAddress((void**)&kb,    g_k);
    cudaGetSymbolAddress((void**)&basis, g_basis);

    // 1. u = LN(LN(x))
    k_double_ln<<<BL_, 256>>>(x, n1_w, n1_b, mn_w, mn_b, u);
    // 2. xz = u @ in_w^T + in_b              (4096 x 2048 x 512)
    k_gemm_tc<128,128,0><<<dim3(16, 32), 256>>>(u, DIM_, in_w, in_b, nullptr, xz, 2048, DIM_);
    // 3. xc = silu(depthwise_conv(xm) + conv_b)
    k_conv_silu<<<BL_*DIN_/256, 256>>>(xz, conv_w, conv_b, xc);
    // 4. dbc = xc @ xp_w^T (split-K=4 partials, then reduce)   (4096 x 64 x 1024)
    k_gemm_tc<64,64,0><<<dim3(1, 64, 4), 256>>>(xc, DIN_, xp_w, nullptr, nullptr, dbcp, 64, DIN_);
    k_red4<<<BL_*64/4/256, 256>>>(dbcp, dbc);
    // 5. delta = softplus(dbc[:, :32] @ dt_w^T + dt_b)   (4096 x 1024 x 32)
    k_gemm_tc<128,128,1><<<dim3(8, 32), 256>>>(dbc, 64, dt_w, dt_b, nullptr, delta, DIN_, 32);
    // 6. SSM scan -> y
    k_scan<<<(B_*DIN_)/16, 256>>>(delta, dbc, xc, A_log, y);
    // 7. gate
    k_gate<<<BL_*DIN_/256, 256>>>(y, xc, xz, D_par);
    // 8. x1 = x + y @ out_w^T + out_b        (4096 x 512 x 1024)
    k_gemm_tc<128,64,2><<<dim3(8, 32), 256>>>(y, DIN_, out_w, out_b, x, x1, DIM_, DIN_);
    // 9. k = LN(LN(x1))
    k_double_ln<<<BL_, 256>>>(x1, n2_w, n2_b, kn_w, kn_b, kb);
    // 10. basis
    k_basis<<<BL_*DIM_/256, 256>>>(kb, grid, basis);
    // 11. out = x1 + basis @ spl_w^T         (4096 x 512 x 4096)
    k_gemm_tc<128,64,2><<<dim3(8, 32), 256>>>(basis, DIM_*NGRID, spl_w, nullptr, x1,
                                              (float*)d_out, DIM_, DIM_*NGRID);
}

// round 9
// speedup vs baseline: 2.0055x; 1.0055x over previous
#include <cuda_runtime.h>
#include <cuda_bf16.h>
#include <math.h>
#include <stdint.h>

#define B_    2
#define L_    2048
#define DIM_  512
#define DIN_  1024
#define BL_   (B_*L_)
#define NGRID 8
#define INV_DEN 3.0303030303030303f

// ---------------- scratch (device globals; no allocation) ----------------
__device__ float g_u    [BL_*DIM_];
__device__ float g_xz   [(size_t)BL_*2048];
__device__ float g_xc   [BL_*DIN_];
__device__ float g_dbc  [BL_*64];
__device__ float g_dbcp [4*BL_*64];           // split-K partials
__device__ float g_delta[BL_*DIN_];
__device__ float g_y    [BL_*DIN_];
__device__ float g_x1   [BL_*DIM_];
__device__ float g_k    [BL_*DIM_];
__device__ float g_basis[(size_t)BL_*4096];

// ---------------- helpers ----------------
__device__ __forceinline__ float softplusf(float x){
    return fmaxf(x, 0.f) + log1pf(expf(-fabsf(x)));
}
__device__ __forceinline__ float siluf(float x){
    return x / (1.f + expf(-x));
}
__device__ __forceinline__ float tf32r(float x){
    uint32_t u;
    asm("cvt.rna.tf32.f32 %0, %1;" : "=r"(u) : "f"(x));
    return __uint_as_float(u);
}
__device__ __forceinline__ void mma_tf32(float (&d)[4], const uint32_t (&a)[4], const uint32_t (&b)[2]){
    asm volatile("mma.sync.aligned.m16n8k8.row.col.f32.tf32.tf32.f32 "
        "{%0,%1,%2,%3}, {%4,%5,%6,%7}, {%8,%9}, {%0,%1,%2,%3};\n"
        : "+f"(d[0]), "+f"(d[1]), "+f"(d[2]), "+f"(d[3])
        : "r"(a[0]), "r"(a[1]), "r"(a[2]), "r"(a[3]), "r"(b[0]), "r"(b[1]));
}

__device__ __forceinline__ void block_reduce2(float& s, float& ss, float* sh){
    #pragma unroll
    for (int o = 16; o; o >>= 1){
        s  += __shfl_xor_sync(0xffffffffu, s,  o);
        ss += __shfl_xor_sync(0xffffffffu, ss, o);
    }
    int w = threadIdx.x >> 5, l = threadIdx.x & 31;
    if (l == 0){ sh[w] = s; sh[8 + w] = ss; }
    __syncthreads();
    if (threadIdx.x < 32){
        float a = (l < 8) ? sh[l]     : 0.f;
        float b = (l < 8) ? sh[8 + l] : 0.f;
        #pragma unroll
        for (int o = 4; o; o >>= 1){
            a += __shfl_xor_sync(0xffffffffu, a, o);
            b += __shfl_xor_sync(0xffffffffu, b, o);
        }
        if (l == 0){ sh[16] = a; sh[17] = b; }
    }
    __syncthreads();
    s = sh[16]; ss = sh[17];
    __syncthreads();
}

// ---------------- double layernorm ----------------
__global__ void k_double_ln(const float* __restrict__ x,
                            const float* __restrict__ w1, const float* __restrict__ b1,
                            const float* __restrict__ w2, const float* __restrict__ b2,
                            float* __restrict__ out)
{
    __shared__ float sh[18];
    const int row = blockIdx.x;
    const int t = threadIdx.x;
    const float* xr = x + (size_t)row * DIM_;
    float v0 = xr[t], v1 = xr[t + 256];
    float s = v0 + v1, ss = v0*v0 + v1*v1;
    block_reduce2(s, ss, sh);
    float mu  = s * (1.f/DIM_);
    float var = ss * (1.f/DIM_) - mu*mu;
    float inv = rsqrtf(var + 1e-5f);
    float y0 = (v0 - mu) * inv * w1[t]       + b1[t];
    float y1 = (v1 - mu) * inv * w1[t + 256] + b1[t + 256];
    s = y0 + y1; ss = y0*y0 + y1*y1;
    block_reduce2(s, ss, sh);
    mu  = s * (1.f/DIM_);
    var = ss * (1.f/DIM_) - mu*mu;
    inv = rsqrtf(var + 1e-5f);
    out[(size_t)row*DIM_ + t]       = (y0 - mu) * inv * w2[t]       + b2[t];
    out[(size_t)row*DIM_ + t + 256] = (y1 - mu) * inv * w2[t + 256] + b2[t + 256];
}

// ---------------- tf32 tensor-core GEMM with register prefetch pipeline ----------------
// C[M,N] = A[M,K] * W[N,K]^T ; grid.z>1 => split-K partials at C + z*M*N.
// EPI: 0=+bias  1=+bias,softplus  2=+bias+residual
template<int BM, int BN, int EPI>
__global__ void __launch_bounds__(256)
k_gemm_tc(const float* __restrict__ A, int lda,
          const float* __restrict__ W,
          const float* __restrict__ bias,
          const float* __restrict__ res,
          float* __restrict__ C, int N, int K)
{
    constexpr int BK  = 16;
    constexpr int PAD = BK + 4;
    constexpr int WM  = BM / 2;
    constexpr int WN  = BN / 4;
    constexpr int MF  = WM / 16;
    constexpr int NF  = WN / 8;
    constexpr int RA  = BM / 64;
    constexpr int RB  = BN / 64;
    __shared__ float As[BM][PAD];
    __shared__ float Bs[BN][PAD];

    const int tid  = threadIdx.x;
    const int bm   = blockIdx.y * BM, bn = blockIdx.x * BN;
    const int wid  = tid >> 5, lane = tid & 31;
    const int wm   = wid >> 2, wn = wid & 3;
    const int g    = lane >> 2, tg = lane & 3;
    const int fr   = tid >> 2;
    const int fk   = (tid & 3) << 2;

    const int klen = K / gridDim.z;
    const int kb   = blockIdx.z * klen;
    const int kend = kb + klen;
    if (gridDim.z > 1) C += (size_t)blockIdx.z * (size_t)(gridDim.y * BM) * N;

    float acc[MF][NF][4];
    #pragma unroll
    for (int i = 0; i < MF; i++)
        #pragma unroll
        for (int j = 0; j < NF; j++)
            #pragma unroll
            for (int c = 0; c < 4; c++) acc[i][j][c] = 0.f;

    float4 rA[RA], rB[RB];
    #pragma unroll
    for (int i = 0; i < RA; i++)
        rA[i] = *(const float4*)&A[(size_t)(bm + i*64 + fr) * lda + kb + fk];
    #pragma unroll
    for (int i = 0; i < RB; i++)
        rB[i] = *(const float4*)&W[(size_t)(bn + i*64 + fr) * K + kb + fk];

    for (int k0 = kb; k0 < kend; k0 += BK){
        #pragma unroll
        for (int i = 0; i < RA; i++)
            *(float4*)&As[i*64 + fr][fk] =
                make_float4(tf32r(rA[i].x), tf32r(rA[i].y), tf32r(rA[i].z), tf32r(rA[i].w));
        #pragma unroll
        for (int i = 0; i < RB; i++)
            *(float4*)&Bs[i*64 + fr][fk] =
                make_float4(tf32r(rB[i].x), tf32r(rB[i].y), tf32r(rB[i].z), tf32r(rB[i].w));
        __syncthreads();
        if (k0 + BK < kend){
            #pragma unroll
            for (int i = 0; i < RA; i++)
                rA[i] = *(const float4*)&A[(size_t)(bm + i*64 + fr) * lda + k0 + BK + fk];
            #pragma unroll
            for (int i = 0; i < RB; i++)
                rB[i] = *(const float4*)&W[(size_t)(bn + i*64 + fr) * K + k0 + BK + fk];
        }
        #pragma unroll
        for (int ks = 0; ks < BK; ks += 8){
            uint32_t a[MF][4], b[NF][2];
            #pragma unroll
            for (int mi = 0; mi < MF; mi++){
                int r = wm * WM + mi * 16 + g;
                a[mi][0] = __float_as_uint(As[r    ][ks + tg    ]);
                a[mi][1] = __float_as_uint(As[r + 8][ks + tg    ]);
                a[mi][2] = __float_as_uint(As[r    ][ks + tg + 4]);
                a[mi][3] = __float_as_uint(As[r + 8][ks + tg + 4]);
            }
            #pragma unroll
            for (int ni = 0; ni < NF; ni++){
                int c = wn * WN + ni * 8 + g;
                b[ni][0] = __float_as_uint(Bs[c][ks + tg    ]);
                b[ni][1] = __float_as_uint(Bs[c][ks + tg + 4]);
            }
            #pragma unroll
            for (int mi = 0; mi < MF; mi++)
                #pragma unroll
                for (int ni = 0; ni < NF; ni++)
                    mma_tf32(acc[mi][ni], a[mi], b[ni]);
        }
        __syncthreads();
    }

    #pragma unroll
    for (int mi = 0; mi < MF; mi++){
        int row0 = bm + wm * WM + mi * 16 + g;
        #pragma unroll
        for (int ni = 0; ni < NF; ni++){
            int col = bn + wn * WN + ni * 8 + 2 * tg;
            float b0 = bias ? bias[col] : 0.f, b1 = bias ? bias[col + 1] : 0.f;
            float v0 = acc[mi][ni][0] + b0, v1 = acc[mi][ni][1] + b1;
            float v2 = acc[mi][ni][2] + b0, v3 = acc[mi][ni][3] + b1;
            if (EPI == 1){ v0 = softplusf(v0); v1 = softplusf(v1); v2 = softplusf(v2); v3 = softplusf(v3); }
            if (EPI == 2){
                const float2 r0 = *(const float2*)&res[(size_t)row0 * N + col];
                const float2 r1 = *(const float2*)&res[(size_t)(row0 + 8) * N + col];
                v0 += r0.x; v1 += r0.y; v2 += r1.x; v3 += r1.y;
            }
            *(float2*)&C[(size_t)row0 * N + col]       = make_float2(v0, v1);
            *(float2*)&C[(size_t)(row0 + 8) * N + col] = make_float2(v2, v3);
        }
    }
}

// ---------------- reduce 4 split-K partials ----------------
__global__ void k_red4(const float* __restrict__ p, float* __restrict__ out)
{
    int idx = blockIdx.x * 256 + threadIdx.x;
    const float4* p4 = (const float4*)p;
    const int n4 = BL_ * 64 / 4;
    float4 a = p4[idx], b = p4[idx + n4], c = p4[idx + 2*n4], d = p4[idx + 3*n4];
    ((float4*)out)[idx] = make_float4(a.x+b.x+c.x+d.x, a.y+b.y+c.y+d.y,
                                      a.z+b.z+c.z+d.z, a.w+b.w+c.w+d.w);
}

// ---------------- causal depthwise conv (d_conv=4) + bias + SiLU ----------------
__global__ void k_conv_silu(const float* __restrict__ xz,
                            const float* __restrict__ cw,
                            const float* __restrict__ cb,
                            float* __restrict__ xc)
{
    int idx = blockIdx.x * 256 + threadIdx.x;
    int d = idx & (DIN_ - 1);
    int t = idx >> 10;
    int l = t & (L_ - 1);
    const float* w = cw + d * 4;
    float acc = cb[d];
    #pragma unroll
    for (int k = 0; k < 4; k++){
        int ls = l + k - 3;
        if (ls >= 0)
            acc = fmaf(xz[(size_t)(t + k - 3) * 2048 + d], w[k], acc);
    }
    xc[idx] = siluf(acc);
}

// ---------------- SSM sequential scan (store-only divergent branch) ----------------
__global__ void k_scan(const float* __restrict__ delta,
                       const float* __restrict__ dbc,
                       const float* __restrict__ xc,
                       const float* __restrict__ A_log,
                       float* __restrict__ y)
{
    const int tid = threadIdx.x;
    const int n  = tid & 15;
    const int ch = blockIdx.x * 16 + (tid >> 4);
    const int b  = ch >> 10;
    const int d  = ch & (DIN_ - 1);
    const float A = -expf(A_log[d * 16 + n]);
    float h = 0.f;
    const int tbase = b * L_;
    for (int l = 0; l < L_; l++){
        const int t = tbase + l;
        float dlt = delta[(size_t)t * DIN_ + d];
        float xcv = xc   [(size_t)t * DIN_ + d];
        float Bv  = dbc[(size_t)t * 64 + 32 + n];
        float Cv  = dbc[(size_t)t * 64 + 48 + n];
        h = __expf(dlt * A) * h + dlt * Bv * xcv;
        float p = h * Cv;
        p += __shfl_xor_sync(0xffffffffu, p, 8);
        p += __shfl_xor_sync(0xffffffffu, p, 4);
        p += __shfl_xor_sync(0xffffffffu, p, 2);
        p += __shfl_xor_sync(0xffffffffu, p, 1);
        if (n == 0) y[(size_t)t * DIN_ + d] = p;
    }
}

// ---------------- gate: y <- (y + D*xc) * silu(z) ----------------
__global__ void k_gate(float* __restrict__ y,
                       const float* __restrict__ xc,
                       const float* __restrict__ xz,
                       const float* __restrict__ Dp)
{
    int idx = blockIdx.x * 256 + threadIdx.x;
    int d = idx & (DIN_ - 1);
    int t = idx >> 10;
    float z  = xz[(size_t)t * 2048 + DIN_ + d];
    float yv = y[idx] + Dp[d] * xc[idx];
    y[idx] = yv * siluf(z);
}

// ---------------- KAN basis ----------------
__global__ void k_basis(const float* __restrict__ k,
                        const float* __restrict__ grid,
                        float* __restrict__ basis)
{
    int idx = blockIdx.x * 256 + threadIdx.x;
    float kv = k[idx];
    float o[NGRID];
    #pragma unroll
    for (int g = 0; g < NGRID; g++){
        float tt = tanhf((kv - grid[g]) * INV_DEN);
        o[g] = 1.f - tt * tt;
    }
    float4* bp = (float4*)(basis + (size_t)idx * NGRID);
    bp[0] = make_float4(o[0], o[1], o[2], o[3]);
    bp[1] = make_float4(o[4], o[5], o[6], o[7]);
}

// ---------------- launch ----------------
extern "C" void kernel_launch(void* const* d_in, const int* in_sizes, int n_in,
                              void* d_out, int out_size)
{
    const float* x      = (const float*)d_in[0];
    const float* n1_w   = (const float*)d_in[1];
    const float* n1_b   = (const float*)d_in[2];
    const float* mn_w   = (const float*)d_in[3];
    const float* mn_b   = (const float*)d_in[4];
    const float* in_w   = (const float*)d_in[5];
    const float* in_b   = (const float*)d_in[6];
    const float* conv_w = (const float*)d_in[7];
    const float* conv_b = (const float*)d_in[8];
    const float* xp_w   = (const float*)d_in[9];
    const float* dt_w   = (const float*)d_in[10];
    const float* dt_b   = (const float*)d_in[11];
    const float* A_log  = (const float*)d_in[12];
    const float* D_par  = (const float*)d_in[13];
    const float* out_w  = (const float*)d_in[14];
    const float* out_b  = (const float*)d_in[15];
    const float* n2_w   = (const float*)d_in[16];
    const float* n2_b   = (const float*)d_in[17];
    const float* kn_w   = (const float*)d_in[18];
    const float* kn_b   = (const float*)d_in[19];
    const float* grid   = (const float*)d_in[20];
    const float* spl_w  = (const float*)d_in[21];

    float *u, *xz, *xc, *dbc, *dbcp, *delta, *y, *x1, *kb, *basis;
    cudaGetSymbolAddress((void**)&u,     g_u);
    cudaGetSymbolAddress((void**)&xz,    g_xz);
    cudaGetSymbolAddress((void**)&xc,    g_xc);
    cudaGetSymbolAddress((void**)&dbc,   g_dbc);
    cudaGetSymbolAddress((void**)&dbcp,  g_dbcp);
    cudaGetSymbolAddress((void**)&delta, g_delta);
    cudaGetSymbolAddress((void**)&y,     g_y);
    cudaGetSymbolAddress((void**)&x1,    g_x1);
    cudaGetSymbolAddress((void**)&kb,    g_k);
    cudaGetSymbolAddress((void**)&basis, g_basis);

    // 1. u = LN(LN(x))
    k_double_ln<<<BL_, 256>>>(x, n1_w, n1_b, mn_w, mn_b, u);
    // 2. xz = u @ in_w^T + in_b              (4096 x 2048 x 512)
    k_gemm_tc<128,128,0><<<dim3(16, 32), 256>>>(u, DIM_, in_w, in_b, nullptr, xz, 2048, DIM_);
    // 3. xc = silu(depthwise_conv(xm) + conv_b)
    k_conv_silu<<<BL_*DIN_/256, 256>>>(xz, conv_w, conv_b, xc);
    // 4. dbc = xc @ xp_w^T (split-K=4 partials, then reduce)   (4096 x 64 x 1024)
    k_gemm_tc<64,64,0><<<dim3(1, 64, 4), 256>>>(xc, DIN_, xp_w, nullptr, nullptr, dbcp, 64, DIN_);
    k_red4<<<BL_*64/4/256, 256>>>(dbcp, dbc);
    // 5. delta = softplus(dbc[:, :32] @ dt_w^T + dt_b)   (4096 x 1024 x 32)
    k_gemm_tc<128,128,1><<<dim3(8, 32), 256>>>(dbc, 64, dt_w, dt_b, nullptr, delta, DIN_, 32);
    // 6. SSM scan -> y
    k_scan<<<(B_*DIN_)/16, 256>>>(delta, dbc, xc, A_log, y);
    // 7. gate
    k_gate<<<BL_*DIN_/256, 256>>>(y, xc, xz, D_par);
    // 8. x1 = x + y @ out_w^T + out_b        (4096 x 512 x 1024)
    k_gemm_tc<128,64,2><<<dim3(8, 32), 256>>>(y, DIN_, out_w, out_b, x, x1, DIM_, DIN_);
    // 9. k = LN(LN(x1))
    k_double_ln<<<BL_, 256>>>(x1, n2_w, n2_b, kn_w, kn_b, kb);
    // 10. basis
    k_basis<<<BL_*DIM_/256, 256>>>(kb, grid, basis);
    // 11. out = x1 + basis @ spl_w^T         (4096 x 512 x 4096)
    k_gemm_tc<128,64,2><<<dim3(8, 32), 256>>>(basis, DIM_*NGRID, spl_w, nullptr, x1,
                                              (float*)d_out, DIM_, DIM_*NGRID);
}